// round 12
// baseline (speedup 1.0000x reference)
#include <cuda_runtime.h>
#include <cuda_bf16.h>
#include <stdint.h>

// ----------------------------------------------------------------------------
// SpectralPooling via HMMA (mma.sync m16n8k16 bf16, 3-term split) GEMMs.
// y = idctn(pad(crop(dctn(x)))); axes 0,1 cancel. Per-axis operator
// B[o][i] = sum_{k<28} D32[k,o]*D64[k,i]  (32x64), applied along axes 2,3,4.
// Three stages, each GEMM [rows x 64] -> [rows x 32] against B^T; outputs are
// written "pre-transposed" so K is always contiguous and stores coalesce:
//   stage1 (SB=12): X[b][i0][i1][i2]   -> T1[b][o2][i0][i1]
//   stage2 (SB=11): T1[b][o2][i0][i1]  -> T2[b][o1][o2][i0]
//   stage3 (SB=10): T2[b][o1][o2][i0]  -> Y[b][o0][o1][o2]
// out_addr(m,c) = (m>>SB)*(32<<SB) + c*(1<<SB) + (m & ((1<<SB)-1))
// Precision: D = Ah*Bh + Ah*Bl + Al*Bh (bf16 hi/lo splits, fp32 accumulate).
// SW128-swizzled smem (no padding): 40 KB/CTA -> 5 CTAs/SM (was smem-capped
// at 4). Full-MLP loader; ldmatrix.x4 fragments.
// ----------------------------------------------------------------------------

#define SW128(off) ((off) ^ (((off) >> 3) & 0x70))

__device__ __nv_bfloat16 g_Bh[2048];   // B hi, row-major [o][i] (32x64)
__device__ __nv_bfloat16 g_Bl[2048];   // B lo
__device__ float g_T1[33554432];       // 128 MB scratch
__device__ float g_T2[16777216];       //  64 MB scratch

__device__ __forceinline__ uint32_t smem_u32(const void* p) {
    uint32_t a;
    asm("{ .reg .u64 t; cvta.to.shared.u64 t, %1; cvt.u32.u64 %0, t; }"
        : "=r"(a) : "l"(p));
    return a;
}

// ---------------- init: one warp per B element, lane = k-term -------------------
__global__ void init_B_kernel() {
    int gw   = (blockIdx.x * blockDim.x + threadIdx.x) >> 5;  // 0..2047
    int lane = threadIdx.x & 31;
    if (gw >= 2048) return;
    int o = gw >> 6;   // 0..31
    int i = gw & 63;   // 0..63
    float term = 0.0f;
    if (lane < 28) {
        const float s32_0 = 0.17677669529663688f;  // sqrt(1/32)
        const float s32_k = 0.25f;                 // sqrt(2/32)
        const float s64_0 = 0.125f;                // sqrt(1/64)
        const float s64_k = 0.17677669529663688f;  // sqrt(2/64)
        float a32 = (2.0f * o + 1.0f) * (float)lane / 64.0f;
        float a64 = (2.0f * i + 1.0f) * (float)lane / 128.0f;
        float d32 = ((lane == 0) ? s32_0 : s32_k) * cospif(a32);
        float d64 = ((lane == 0) ? s64_0 : s64_k) * cospif(a64);
        term = d32 * d64;
    }
    #pragma unroll
    for (int s = 16; s > 0; s >>= 1)
        term += __shfl_xor_sync(0xFFFFFFFFu, term, s);
    if (lane == 0) {
        __nv_bfloat16 h = __float2bfloat16(term);
        float lo = term - __bfloat162float(h);
        g_Bh[gw] = h;
        g_Bl[gw] = __float2bfloat16(lo);
    }
}

// ---------------- mma.sync / ldmatrix wrappers ------------------------------------
__device__ __forceinline__ void mma16816(float* d, const uint32_t* a,
                                         const uint32_t* b) {
    asm("mma.sync.aligned.m16n8k16.row.col.f32.bf16.bf16.f32 "
        "{%0,%1,%2,%3}, {%4,%5,%6,%7}, {%8,%9}, {%0,%1,%2,%3};"
        : "+f"(d[0]), "+f"(d[1]), "+f"(d[2]), "+f"(d[3])
        : "r"(a[0]), "r"(a[1]), "r"(a[2]), "r"(a[3]), "r"(b[0]), "r"(b[1]));
}

__device__ __forceinline__ void ldsm4(uint32_t* r, uint32_t addr) {
    asm volatile("ldmatrix.sync.aligned.m8n8.x4.shared.b16 {%0,%1,%2,%3}, [%4];"
                 : "=r"(r[0]), "=r"(r[1]), "=r"(r[2]), "=r"(r[3]) : "r"(addr));
}

// ---------------- stage kernel --------------------------------------------------
// smem arena (40960 B -> 5 CTAs/SM):
//   [0,16384)      sAh 128x64 bf16, SW128 swizzled
//   [16384,32768)  sAl
//   [32768,36864)  sBh  32x64 bf16, SW128 swizzled
//   [36864,40960)  sBl
//   epilogue: fp32 ep[128][33] (16896 B) aliases sAh+sAl after mainloop.
template<int SB>
__global__ __launch_bounds__(128, 5) void stage_kernel(
        const float* __restrict__ xin, float* __restrict__ xout) {
    const float* in = (SB == 12) ? xin : (SB == 11 ? (const float*)g_T1
                                                   : (const float*)g_T2);
    float* out      = (SB == 12) ? (float*)g_T1
                                 : (SB == 11 ? (float*)g_T2 : xout);
    constexpr size_t OC = (size_t)1 << SB;

    __shared__ __align__(128) char arena[40960];
    char* sAh = arena;
    char* sAl = arena + 16384;
    char* sBh = arena + 32768;
    char* sBl = arena + 36864;

    const int tid = threadIdx.x;
    const int w   = tid >> 5;
    const int lid = tid & 31;
    const int gid = lid >> 2;   // 0..7
    const int tg  = lid & 3;    // 0..3

    // ---- load B hi/lo, swizzled (4B stores, conflict-free: 32 lanes = 1 row)
    {
        const uint32_t* bh = (const uint32_t*)g_Bh;
        const uint32_t* bl = (const uint32_t*)g_Bl;
        #pragma unroll
        for (int idx = tid; idx < 1024; idx += 128) {
            int r = idx >> 5, c2 = idx & 31;
            uint32_t sw = SW128((uint32_t)(r * 128 + c2 * 4));
            *(uint32_t*)(sBh + sw) = bh[idx];
            *(uint32_t*)(sBl + sw) = bl[idx];
        }
    }

    // ---- load A tile (2048 float4), full MLP, split hi/lo, swizzled STS
    {
        const float4* __restrict__ inp =
            (const float4*)(in + (size_t)blockIdx.x * 8192);
        #pragma unroll
        for (int j = 0; j < 16; ++j) {
            int f = j * 128 + tid;           // float4 index 0..2047
            float4 v = inp[f];
            int r = f >> 4, k4 = f & 15;
            uint32_t sw = SW128((uint32_t)(r * 128 + k4 * 8));
            uint32_t h01, h23, l01, l23;
            asm("cvt.rn.bf16x2.f32 %0, %1, %2;" : "=r"(h01) : "f"(v.y), "f"(v.x));
            asm("cvt.rn.bf16x2.f32 %0, %1, %2;" : "=r"(h23) : "f"(v.w), "f"(v.z));
            float hx = __uint_as_float(h01 << 16);
            float hy = __uint_as_float(h01 & 0xFFFF0000u);
            float hz = __uint_as_float(h23 << 16);
            float hw = __uint_as_float(h23 & 0xFFFF0000u);
            asm("cvt.rn.bf16x2.f32 %0, %1, %2;" : "=r"(l01)
                : "f"(v.y - hy), "f"(v.x - hx));
            asm("cvt.rn.bf16x2.f32 %0, %1, %2;" : "=r"(l23)
                : "f"(v.w - hw), "f"(v.z - hz));
            *(uint2*)(sAh + sw) = make_uint2(h01, h23);
            *(uint2*)(sAl + sw) = make_uint2(l01, l23);
        }
    }
    __syncthreads();

    // ---- per-lane ldmatrix addressing (swizzled per access)
    const int lr = lid & 7, mi = lid >> 3;
    const uint32_t uAh = smem_u32(sAh), uAl = smem_u32(sAl);
    const uint32_t uBh = smem_u32(sBh), uBl = smem_u32(sBl);
    const int arow = w * 32 + ((mi & 1) << 3) + lr;   // + rt*16
    const int brow = ((mi >> 1) << 3) + lr;           // + t*16
    const int acc_k = (mi >> 1);                      // A k-chunk half
    const int bcc_k = (mi & 1);                       // B k-chunk half

    // ---- HMMA mainloop: acc[rt][nt][4]
    float acc[2][4][4];
    #pragma unroll
    for (int rt = 0; rt < 2; ++rt)
        #pragma unroll
        for (int nt = 0; nt < 4; ++nt)
            #pragma unroll
            for (int q = 0; q < 4; ++q) acc[rt][nt][q] = 0.0f;

    #pragma unroll
    for (int kk = 0; kk < 4; ++kk) {
        uint32_t ah[2][4], al[2][4];
        #pragma unroll
        for (int rt = 0; rt < 2; ++rt) {
            uint32_t ao = SW128((uint32_t)((arow + rt * 16) * 128
                                           + (kk * 2 + acc_k) * 16));
            ldsm4(ah[rt], uAh + ao);
            ldsm4(al[rt], uAl + ao);
        }
        uint32_t bh[4][2], bl[4][2];
        #pragma unroll
        for (int t = 0; t < 2; ++t) {
            uint32_t bo = SW128((uint32_t)((brow + t * 16) * 128
                                           + (kk * 2 + bcc_k) * 16));
            uint32_t rh[4], rl[4];
            ldsm4(rh, uBh + bo);
            ldsm4(rl, uBl + bo);
            bh[2 * t][0] = rh[0]; bh[2 * t][1] = rh[1];
            bh[2 * t + 1][0] = rh[2]; bh[2 * t + 1][1] = rh[3];
            bl[2 * t][0] = rl[0]; bl[2 * t][1] = rl[1];
            bl[2 * t + 1][0] = rl[2]; bl[2 * t + 1][1] = rl[3];
        }
        #pragma unroll
        for (int rt = 0; rt < 2; ++rt)
            #pragma unroll
            for (int nt = 0; nt < 4; ++nt) {
                mma16816(acc[rt][nt], ah[rt], bh[nt]);   // Ah*Bh
                mma16816(acc[rt][nt], ah[rt], bl[nt]);   // Ah*Bl
                mma16816(acc[rt][nt], al[rt], bh[nt]);   // Al*Bh
            }
    }

    // ---- epilogue: transpose through ep[128][33] fp32 (aliases sAh+sAl)
    __syncthreads();               // all warps done with A smem
    float* ep = (float*)arena;
    #pragma unroll
    for (int rt = 0; rt < 2; ++rt)
        #pragma unroll
        for (int nt = 0; nt < 4; ++nt) {
            int r0 = w * 32 + rt * 16 + gid;
            int c0 = nt * 8 + tg * 2;
            ep[r0 * 33 + c0]           = acc[rt][nt][0];
            ep[r0 * 33 + c0 + 1]       = acc[rt][nt][1];
            ep[(r0 + 8) * 33 + c0]     = acc[rt][nt][2];
            ep[(r0 + 8) * 33 + c0 + 1] = acc[rt][nt][3];
        }
    __syncwarp();

    // ---- coalesced transposed store (per-warp rows, own region)
    size_t m = (size_t)blockIdx.x * 128 + (size_t)(w * 32 + lid);
    float* __restrict__ ob = out + (m >> SB) * (OC * 32) + (m & (OC - 1));
    const float* eprow = ep + (w * 32 + lid) * 33;
    #pragma unroll
    for (int c = 0; c < 32; ++c)
        ob[(size_t)c << SB] = eprow[c];
}

// ---------------- launch ---------------------------------------------------------
extern "C" void kernel_launch(void* const* d_in, const int* in_sizes, int n_in,
                              void* d_out, int out_size) {
    const float* x = (const float*)d_in[0];
    float* out = (float*)d_out;

    init_B_kernel<<<512, 128>>>();

    stage_kernel<12><<<8192, 128>>>(x, out);   // X  -> T1   (contract i2)
    stage_kernel<11><<<4096, 128>>>(x, out);   // T1 -> T2   (contract i1)
    stage_kernel<10><<<2048, 128>>>(x, out);   // T2 -> out  (contract i0)
}

// round 13
// speedup vs baseline: 1.6078x; 1.6078x over previous
#include <cuda_runtime.h>
#include <cuda_fp16.h>
#include <stdint.h>

// ----------------------------------------------------------------------------
// SpectralPooling via HMMA (mma.sync m16n8k16 fp16, 2-term B-split) GEMMs.
// y = idctn(pad(crop(dctn(x)))); axes 0,1 cancel. Per-axis operator
// B[o][i] = sum_{k<28} D32[k,o]*D64[k,i]  (32x64), applied along axes 2,3,4.
// Three stages, each GEMM [rows x 64] -> [rows x 32] against B^T; outputs are
// written "pre-transposed" so K is always contiguous and stores coalesce:
//   stage1 (SB=12): X[b][i0][i1][i2]   -> T1[b][o2][i0][i1]   (fp16)
//   stage2 (SB=11): T1[b][o2][i0][i1]  -> T2[b][o1][o2][i0]   (fp16)
//   stage3 (SB=10): T2[b][o1][o2][i0]  -> Y[b][o0][o1][o2]    (fp32)
// out_addr(m,c) = (m>>SB)*(32<<SB) + c*(1<<SB) + (m & ((1<<SB)-1))  [elements]
// Precision: A plain fp16 (repr err ~2^-12/stage), B = Bh + Bl fp16 split
// (residual ~2^-24): D = A*Bh + A*Bl, fp32 accumulate. Predicted rel ~3e-4.
// 8 MMAs/warp/k-step (was 12), A-smem halved, intermediates halved.
// ----------------------------------------------------------------------------

__device__ __half g_Bh[2048];      // B hi, row-major [o][i] (32x64)
__device__ __half g_Bl[2048];      // B lo
__device__ __half g_T1[33554432];  // 64 MB
__device__ __half g_T2[16777216];  // 32 MB

__device__ __forceinline__ uint32_t smem_u32(const void* p) {
    uint32_t a;
    asm("{ .reg .u64 t; cvta.to.shared.u64 t, %1; cvt.u32.u64 %0, t; }"
        : "=r"(a) : "l"(p));
    return a;
}

// ---------------- init: one warp per B element, lane = k-term -------------------
__global__ void init_B_kernel() {
    int gw   = (blockIdx.x * blockDim.x + threadIdx.x) >> 5;  // 0..2047
    int lane = threadIdx.x & 31;
    if (gw >= 2048) return;
    int o = gw >> 6;   // 0..31
    int i = gw & 63;   // 0..63
    float term = 0.0f;
    if (lane < 28) {
        const float s32_0 = 0.17677669529663688f;  // sqrt(1/32)
        const float s32_k = 0.25f;                 // sqrt(2/32)
        const float s64_0 = 0.125f;                // sqrt(1/64)
        const float s64_k = 0.17677669529663688f;  // sqrt(2/64)
        float a32 = (2.0f * o + 1.0f) * (float)lane / 64.0f;
        float a64 = (2.0f * i + 1.0f) * (float)lane / 128.0f;
        float d32 = ((lane == 0) ? s32_0 : s32_k) * cospif(a32);
        float d64 = ((lane == 0) ? s64_0 : s64_k) * cospif(a64);
        term = d32 * d64;
    }
    #pragma unroll
    for (int s = 16; s > 0; s >>= 1)
        term += __shfl_xor_sync(0xFFFFFFFFu, term, s);
    if (lane == 0) {
        __half h = __float2half_rn(term);
        float lo = term - __half2float(h);
        g_Bh[gw] = h;
        g_Bl[gw] = __float2half_rn(lo);
    }
}

// ---------------- mma.sync / ldmatrix wrappers ------------------------------------
__device__ __forceinline__ void mma16816(float* d, const uint32_t* a,
                                         const uint32_t* b) {
    asm("mma.sync.aligned.m16n8k16.row.col.f32.f16.f16.f32 "
        "{%0,%1,%2,%3}, {%4,%5,%6,%7}, {%8,%9}, {%0,%1,%2,%3};"
        : "+f"(d[0]), "+f"(d[1]), "+f"(d[2]), "+f"(d[3])
        : "r"(a[0]), "r"(a[1]), "r"(a[2]), "r"(a[3]), "r"(b[0]), "r"(b[1]));
}

__device__ __forceinline__ void ldsm4(uint32_t* r, uint32_t addr) {
    asm volatile("ldmatrix.sync.aligned.m8n8.x4.shared.b16 {%0,%1,%2,%3}, [%4];"
                 : "=r"(r[0]), "=r"(r[1]), "=r"(r[2]), "=r"(r[3]) : "r"(addr));
}

__device__ __forceinline__ uint32_t cvt_f16x2(float hi, float lo) {
    uint32_t p;
    asm("cvt.rn.f16x2.f32 %0, %1, %2;" : "=r"(p) : "f"(hi), "f"(lo));
    return p;
}

// ---------------- stage kernel --------------------------------------------------
// A tile: 128 rows x 64 K fp16 in smem, padded row stride 72 fp16 (144 B).
// Warp w computes rows w*32..w*32+31, all 32 output cols.
// smem: sA 18 KB + sBh 4.5 KB + sBl 4.5 KB = 27 KB.
template<int SB>
__global__ __launch_bounds__(128, 5) void stage_kernel(
        const float* __restrict__ xin, float* __restrict__ xout) {
    constexpr bool FIN  = (SB == 12);   // fp32 input (convert in loader)
    constexpr bool FOUT = (SB == 10);   // fp32 output
    constexpr size_t OC = (size_t)1 << SB;   // elements per output column line

    const __half* in16 = (SB == 11) ? g_T1 : g_T2;
    __half* out16      = (SB == 12) ? g_T1 : g_T2;

    __shared__ __align__(16) __half sA[128 * 72];   // 18 KB
    __shared__ __align__(16) __half sBh[32 * 72];   // 4.5 KB
    __shared__ __align__(16) __half sBl[32 * 72];   // 4.5 KB

    const int tid = threadIdx.x;
    const int w   = tid >> 5;
    const int lid = tid & 31;
    const int gid = lid >> 2;   // 0..7
    const int tg  = lid & 3;    // 0..3

    // ---- load B hi/lo into padded smem (row stride 144 B)
    {
        const uint32_t* bh = (const uint32_t*)g_Bh;
        const uint32_t* bl = (const uint32_t*)g_Bl;
        #pragma unroll
        for (int idx = tid; idx < 1024; idx += 128) {
            int r = idx >> 5, c2 = idx & 31;
            *(uint32_t*)((char*)sBh + r * 144 + c2 * 4) = bh[idx];
            *(uint32_t*)((char*)sBl + r * 144 + c2 * 4) = bl[idx];
        }
    }

    // ---- load A tile
    if (FIN) {
        // fp32 input: 2048 float4, convert to fp16 pairs
        const float4* __restrict__ inp =
            (const float4*)(xin + (size_t)blockIdx.x * 8192);
        #pragma unroll
        for (int j = 0; j < 16; ++j) {
            int f = j * 128 + tid;           // float4 index 0..2047
            float4 v = inp[f];
            int r = f >> 4, k4 = f & 15;
            uint32_t p01 = cvt_f16x2(v.y, v.x);
            uint32_t p23 = cvt_f16x2(v.w, v.z);
            *(uint2*)((char*)sA + r * 144 + k4 * 8) = make_uint2(p01, p23);
        }
    } else {
        // fp16 input: 1024 uint4 (16 B = 8 fp16), straight copy
        const uint4* __restrict__ inp =
            (const uint4*)(in16 + (size_t)blockIdx.x * 8192);
        #pragma unroll
        for (int j = 0; j < 8; ++j) {
            int f = j * 128 + tid;           // uint4 index 0..1023
            uint4 v = inp[f];
            int r = f >> 3, c8 = f & 7;
            *(uint4*)((char*)sA + r * 144 + c8 * 16) = v;
        }
    }
    __syncthreads();

    // ---- per-lane ldmatrix addressing (padded rows, static offsets)
    const int lr = lid & 7, mi = lid >> 3;
    const uint32_t uA  = smem_u32(sA);
    const uint32_t uBh = smem_u32(sBh), uBl = smem_u32(sBl);
    const uint32_t aoff0 =
        (uint32_t)(w * 32 + ((mi & 1) << 3) + lr) * 144u + ((mi >> 1) << 4);
    const uint32_t boff0 =
        (uint32_t)(((mi >> 1) << 3) + lr) * 144u + ((mi & 1) << 4);

    // ---- HMMA mainloop: acc[rt][nt][4], 2 products (A*Bh, A*Bl)
    float acc[2][4][4];
    #pragma unroll
    for (int rt = 0; rt < 2; ++rt)
        #pragma unroll
        for (int nt = 0; nt < 4; ++nt)
            #pragma unroll
            for (int q = 0; q < 4; ++q) acc[rt][nt][q] = 0.0f;

    #pragma unroll
    for (int kk = 0; kk < 4; ++kk) {
        uint32_t ah[2][4];
        #pragma unroll
        for (int rt = 0; rt < 2; ++rt) {
            uint32_t ao = aoff0 + (uint32_t)(rt * 16 * 144) + (uint32_t)(kk * 32);
            ldsm4(ah[rt], uA + ao);
        }
        uint32_t bh[4][2], bl[4][2];
        #pragma unroll
        for (int t = 0; t < 2; ++t) {
            uint32_t bo = boff0 + (uint32_t)(t * 16 * 144) + (uint32_t)(kk * 32);
            uint32_t rh[4], rl[4];
            ldsm4(rh, uBh + bo);
            ldsm4(rl, uBl + bo);
            bh[2 * t][0] = rh[0]; bh[2 * t][1] = rh[1];
            bh[2 * t + 1][0] = rh[2]; bh[2 * t + 1][1] = rh[3];
            bl[2 * t][0] = rl[0]; bl[2 * t][1] = rl[1];
            bl[2 * t + 1][0] = rl[2]; bl[2 * t + 1][1] = rl[3];
        }
        #pragma unroll
        for (int rt = 0; rt < 2; ++rt)
            #pragma unroll
            for (int nt = 0; nt < 4; ++nt) {
                mma16816(acc[rt][nt], ah[rt], bh[nt]);   // A*Bh
                mma16816(acc[rt][nt], ah[rt], bl[nt]);   // A*Bl
            }
    }

    // ---- epilogue: transpose through this warp's own (dead) A region
    __syncwarp();
    float* epw = (float*)((char*)sA + (size_t)w * 32 * 144);   // 32x33 fp32 fits
    #pragma unroll
    for (int rt = 0; rt < 2; ++rt)
        #pragma unroll
        for (int nt = 0; nt < 4; ++nt) {
            int r0 = rt * 16 + gid;
            int c0 = nt * 8 + tg * 2;
            epw[r0 * 33 + c0]           = acc[rt][nt][0];
            epw[r0 * 33 + c0 + 1]       = acc[rt][nt][1];
            epw[(r0 + 8) * 33 + c0]     = acc[rt][nt][2];
            epw[(r0 + 8) * 33 + c0 + 1] = acc[rt][nt][3];
        }
    __syncwarp();

    // ---- coalesced transposed store
    const size_t M0 = (size_t)blockIdx.x * 128;
    const size_t obase = (M0 >> SB) * (OC * 32) + (M0 & (OC - 1));

    if (FOUT) {
        // fp32 output, one column element per iteration
        float* __restrict__ ob = xout + obase + (size_t)(w * 32 + lid);
        const float* eprow = epw + lid * 33;
        #pragma unroll
        for (int c = 0; c < 32; ++c)
            ob[(size_t)c << SB] = eprow[c];
    } else {
        // fp16 output: pack adjacent m-pair into one 4B store
        uint32_t* __restrict__ o32 = (uint32_t*)out16;
        const int cg = lid >> 4;     // 0..1
        const int mp = lid & 15;     // 0..15 -> rows 2mp, 2mp+1
        #pragma unroll
        for (int j = 0; j < 16; ++j) {
            int c = 2 * j + cg;
            float v0 = epw[(2 * mp) * 33 + c];
            float v1 = epw[(2 * mp + 1) * 33 + c];
            uint32_t p = cvt_f16x2(v1, v0);   // low half = even m
            size_t elem = obase + (size_t)c * OC + (size_t)(w * 32 + 2 * mp);
            o32[elem >> 1] = p;
        }
    }
}

// ---------------- launch ---------------------------------------------------------
extern "C" void kernel_launch(void* const* d_in, const int* in_sizes, int n_in,
                              void* d_out, int out_size) {
    const float* x = (const float*)d_in[0];
    float* out = (float*)d_out;

    init_B_kernel<<<512, 128>>>();

    stage_kernel<12><<<8192, 128>>>(x, out);   // X  -> T1   (contract i2)
    stage_kernel<11><<<4096, 128>>>(x, out);   // T1 -> T2   (contract i1)
    stage_kernel<10><<<2048, 128>>>(x, out);   // T2 -> out  (contract i0)
}

// round 14
// speedup vs baseline: 1.7526x; 1.0901x over previous
#include <cuda_runtime.h>
#include <cuda_fp16.h>
#include <stdint.h>

// ----------------------------------------------------------------------------
// SpectralPooling via HMMA (mma.sync m16n8k16 fp16, single product) GEMMs.
// y = idctn(pad(crop(dctn(x)))); axes 0,1 cancel. Per-axis operator
// B[o][i] = sum_{k<28} D32[k,o]*D64[k,i]  (32x64), applied along axes 2,3,4.
// Three stages, each GEMM [rows x 64] -> [rows x 32] against B^T; outputs are
// written "pre-transposed" so K is always contiguous and stores coalesce:
//   stage1 (SB=12): X[b][i0][i1][i2]   -> T1[b][o2][i0][i1]   (fp16)
//   stage2 (SB=11): T1[b][o2][i0][i1]  -> T2[b][o1][o2][i0]   (fp16)
//   stage3 (SB=10): T2[b][o1][o2][i0]  -> Y[b][o0][o1][o2]    (fp32)
// out_addr(m,c) = (m>>SB)*(32<<SB) + c*(1<<SB) + (m & ((1<<SB)-1))  [elements]
// Precision: A and B plain fp16, fp32 accumulate. Per-stage rounding ~2^-12
// each for A and B -> predicted rel ~5e-4 (measured 3.6e-4 for A-only).
// Stage-2/3 A tiles copied with cp.async (no conversion, no reg pass).
// ----------------------------------------------------------------------------

__device__ __half g_Bh[2048];      // B fp16, row-major [o][i] (32x64)
__device__ __half g_T1[33554432];  // 64 MB
__device__ __half g_T2[16777216];  // 32 MB

__device__ __forceinline__ uint32_t smem_u32(const void* p) {
    uint32_t a;
    asm("{ .reg .u64 t; cvta.to.shared.u64 t, %1; cvt.u32.u64 %0, t; }"
        : "=r"(a) : "l"(p));
    return a;
}

// ---------------- init: one warp per B element, lane = k-term -------------------
__global__ void init_B_kernel() {
    int gw   = (blockIdx.x * blockDim.x + threadIdx.x) >> 5;  // 0..2047
    int lane = threadIdx.x & 31;
    if (gw >= 2048) return;
    int o = gw >> 6;   // 0..31
    int i = gw & 63;   // 0..63
    float term = 0.0f;
    if (lane < 28) {
        const float s32_0 = 0.17677669529663688f;  // sqrt(1/32)
        const float s32_k = 0.25f;                 // sqrt(2/32)
        const float s64_0 = 0.125f;                // sqrt(1/64)
        const float s64_k = 0.17677669529663688f;  // sqrt(2/64)
        float a32 = (2.0f * o + 1.0f) * (float)lane / 64.0f;
        float a64 = (2.0f * i + 1.0f) * (float)lane / 128.0f;
        float d32 = ((lane == 0) ? s32_0 : s32_k) * cospif(a32);
        float d64 = ((lane == 0) ? s64_0 : s64_k) * cospif(a64);
        term = d32 * d64;
    }
    #pragma unroll
    for (int s = 16; s > 0; s >>= 1)
        term += __shfl_xor_sync(0xFFFFFFFFu, term, s);
    if (lane == 0)
        g_Bh[gw] = __float2half_rn(term);
}

// ---------------- mma.sync / ldmatrix / cp.async wrappers --------------------------
__device__ __forceinline__ void mma16816(float* d, const uint32_t* a,
                                         const uint32_t* b) {
    asm("mma.sync.aligned.m16n8k16.row.col.f32.f16.f16.f32 "
        "{%0,%1,%2,%3}, {%4,%5,%6,%7}, {%8,%9}, {%0,%1,%2,%3};"
        : "+f"(d[0]), "+f"(d[1]), "+f"(d[2]), "+f"(d[3])
        : "r"(a[0]), "r"(a[1]), "r"(a[2]), "r"(a[3]), "r"(b[0]), "r"(b[1]));
}

__device__ __forceinline__ void ldsm4(uint32_t* r, uint32_t addr) {
    asm volatile("ldmatrix.sync.aligned.m8n8.x4.shared.b16 {%0,%1,%2,%3}, [%4];"
                 : "=r"(r[0]), "=r"(r[1]), "=r"(r[2]), "=r"(r[3]) : "r"(addr));
}

__device__ __forceinline__ uint32_t cvt_f16x2(float hi, float lo) {
    uint32_t p;
    asm("cvt.rn.f16x2.f32 %0, %1, %2;" : "=r"(p) : "f"(hi), "f"(lo));
    return p;
}

__device__ __forceinline__ void cp16(uint32_t dst, const void* src) {
    asm volatile("cp.async.cg.shared.global [%0], [%1], 16;"
                 :: "r"(dst), "l"(src) : "memory");
}

// ---------------- stage kernel --------------------------------------------------
// A tile: 128 rows x 64 K fp16 in smem, padded row stride 72 fp16 (144 B).
// Warp w computes rows w*32..w*32+31, all 32 output cols.
// smem: sA 18 KB + sBh 4.5 KB = 22.5 KB.
template<int SB>
__global__ __launch_bounds__(128, 5) void stage_kernel(
        const float* __restrict__ xin, float* __restrict__ xout) {
    constexpr bool FIN  = (SB == 12);   // fp32 input (convert in loader)
    constexpr bool FOUT = (SB == 10);   // fp32 output
    constexpr size_t OC = (size_t)1 << SB;   // elements per output column line

    const __half* in16 = (SB == 11) ? g_T1 : g_T2;
    __half* out16      = (SB == 12) ? g_T1 : g_T2;

    __shared__ __align__(16) __half sA[128 * 72];   // 18 KB
    __shared__ __align__(16) __half sBh[32 * 72];   // 4.5 KB

    const int tid = threadIdx.x;
    const int w   = tid >> 5;
    const int lid = tid & 31;
    const int gid = lid >> 2;   // 0..7
    const int tg  = lid & 3;    // 0..3

    const uint32_t uA  = smem_u32(sA);
    const uint32_t uBh = smem_u32(sBh);

    // ---- load A tile (kick off first: longest latency)
    if (FIN) {
        // fp32 input: 2048 float4, convert to fp16 pairs
        const float4* __restrict__ inp =
            (const float4*)(xin + (size_t)blockIdx.x * 8192);
        #pragma unroll
        for (int j = 0; j < 16; ++j) {
            int f = j * 128 + tid;           // float4 index 0..2047
            float4 v = inp[f];
            int r = f >> 4, k4 = f & 15;
            uint32_t p01 = cvt_f16x2(v.y, v.x);
            uint32_t p23 = cvt_f16x2(v.w, v.z);
            *(uint2*)((char*)sA + r * 144 + k4 * 8) = make_uint2(p01, p23);
        }
    } else {
        // fp16 input: 1024 x 16B chunks, cp.async straight into padded smem
        const char* src = (const char*)(in16 + (size_t)blockIdx.x * 8192);
        #pragma unroll
        for (int j = 0; j < 8; ++j) {
            int f = j * 128 + tid;           // chunk index 0..1023
            uint32_t d = uA + (uint32_t)(f >> 3) * 144u + (uint32_t)(f & 7) * 16u;
            cp16(d, src + (size_t)f * 16);
        }
        asm volatile("cp.async.commit_group;" ::: "memory");
    }

    // ---- load B into padded smem (row stride 144 B)
    {
        const uint32_t* bh = (const uint32_t*)g_Bh;
        #pragma unroll
        for (int idx = tid; idx < 1024; idx += 128) {
            int r = idx >> 5, c2 = idx & 31;
            *(uint32_t*)((char*)sBh + r * 144 + c2 * 4) = bh[idx];
        }
    }

    if (!FIN)
        asm volatile("cp.async.wait_group 0;" ::: "memory");
    __syncthreads();

    // ---- per-lane ldmatrix addressing (padded rows, static offsets)
    const int lr = lid & 7, mi = lid >> 3;
    const uint32_t aoff0 =
        (uint32_t)(w * 32 + ((mi & 1) << 3) + lr) * 144u + ((mi >> 1) << 4);
    const uint32_t boff0 =
        (uint32_t)(((mi >> 1) << 3) + lr) * 144u + ((mi & 1) << 4);

    // ---- HMMA mainloop: acc[rt][nt][4], single product A*B
    float acc[2][4][4];
    #pragma unroll
    for (int rt = 0; rt < 2; ++rt)
        #pragma unroll
        for (int nt = 0; nt < 4; ++nt)
            #pragma unroll
            for (int q = 0; q < 4; ++q) acc[rt][nt][q] = 0.0f;

    #pragma unroll
    for (int kk = 0; kk < 4; ++kk) {
        uint32_t ah[2][4];
        #pragma unroll
        for (int rt = 0; rt < 2; ++rt) {
            uint32_t ao = aoff0 + (uint32_t)(rt * 16 * 144) + (uint32_t)(kk * 32);
            ldsm4(ah[rt], uA + ao);
        }
        uint32_t bh[4][2];
        #pragma unroll
        for (int t = 0; t < 2; ++t) {
            uint32_t bo = boff0 + (uint32_t)(t * 16 * 144) + (uint32_t)(kk * 32);
            uint32_t rh[4];
            ldsm4(rh, uBh + bo);
            bh[2 * t][0] = rh[0]; bh[2 * t][1] = rh[1];
            bh[2 * t + 1][0] = rh[2]; bh[2 * t + 1][1] = rh[3];
        }
        #pragma unroll
        for (int rt = 0; rt < 2; ++rt)
            #pragma unroll
            for (int nt = 0; nt < 4; ++nt)
                mma16816(acc[rt][nt], ah[rt], bh[nt]);
    }

    // ---- epilogue: transpose through this warp's own (dead) A region
    __syncwarp();
    float* epw = (float*)((char*)sA + (size_t)w * 32 * 144);   // 32x33 fp32 fits
    #pragma unroll
    for (int rt = 0; rt < 2; ++rt)
        #pragma unroll
        for (int nt = 0; nt < 4; ++nt) {
            int r0 = rt * 16 + gid;
            int c0 = nt * 8 + tg * 2;
            epw[r0 * 33 + c0]           = acc[rt][nt][0];
            epw[r0 * 33 + c0 + 1]       = acc[rt][nt][1];
            epw[(r0 + 8) * 33 + c0]     = acc[rt][nt][2];
            epw[(r0 + 8) * 33 + c0 + 1] = acc[rt][nt][3];
        }
    __syncwarp();

    // ---- coalesced transposed store
    const size_t M0 = (size_t)blockIdx.x * 128;
    const size_t obase = (M0 >> SB) * (OC * 32) + (M0 & (OC - 1));

    if (FOUT) {
        // fp32 output, one column element per iteration
        float* __restrict__ ob = xout + obase + (size_t)(w * 32 + lid);
        const float* eprow = epw + lid * 33;
        #pragma unroll
        for (int c = 0; c < 32; ++c)
            ob[(size_t)c << SB] = eprow[c];
    } else {
        // fp16 output: pack adjacent m-pair into one 4B store
        uint32_t* __restrict__ o32 = (uint32_t*)out16;
        const int cg = lid >> 4;     // 0..1
        const int mp = lid & 15;     // 0..15 -> rows 2mp, 2mp+1
        #pragma unroll
        for (int j = 0; j < 16; ++j) {
            int c = 2 * j + cg;
            float v0 = epw[(2 * mp) * 33 + c];
            float v1 = epw[(2 * mp + 1) * 33 + c];
            uint32_t p = cvt_f16x2(v1, v0);   // low half = even m
            size_t elem = obase + (size_t)c * OC + (size_t)(w * 32 + 2 * mp);
            o32[elem >> 1] = p;
        }
    }
}

// ---------------- launch ---------------------------------------------------------
extern "C" void kernel_launch(void* const* d_in, const int* in_sizes, int n_in,
                              void* d_out, int out_size) {
    const float* x = (const float*)d_in[0];
    float* out = (float*)d_out;

    init_B_kernel<<<512, 128>>>();

    stage_kernel<12><<<8192, 128>>>(x, out);   // X  -> T1   (contract i2)
    stage_kernel<11><<<4096, 128>>>(x, out);   // T1 -> T2   (contract i1)
    stage_kernel<10><<<2048, 128>>>(x, out);   // T2 -> out  (contract i0)
}